// round 12
// baseline (speedup 1.0000x reference)
#include <cuda_runtime.h>
#include <math.h>

#define BATCH 256
#define SEQT  2048
#define DIN   57
#define HID   16
#define G4    64
#define BT    (BATCH*SEQT)
#define NRED  512

typedef unsigned long long u64;

// ---------------- scratch (device globals; no allocs allowed) ----------------
__device__ float g_xg[(size_t)BT * G4];    // 128 MiB: layer-0 pre-gates
__device__ float g_h2[(size_t)BT * HID];   //  32 MiB: layer-2 hidden outputs
__device__ float g_part[NRED * 32];        // per-block partial sums (s1 | s2)
__device__ float g_stats[32];              // scale[16] | shift[16]

// ---------------- f32x2 packed helpers ----------------
__device__ __forceinline__ u64 pk2(float lo, float hi) {
    u64 r; asm("mov.b64 %0, {%1, %2};" : "=l"(r) : "f"(lo), "f"(hi)); return r;
}
__device__ __forceinline__ void unpk2(u64 v, float& lo, float& hi) {
    asm("mov.b64 {%0, %1}, %2;" : "=f"(lo), "=f"(hi) : "l"(v));
}
__device__ __forceinline__ u64 ffma2(u64 a, u64 b, u64 c) {
    u64 r; asm("fma.rn.f32x2 %0, %1, %2, %3;" : "=l"(r) : "l"(a), "l"(b), "l"(c)); return r;
}
__device__ __forceinline__ float hsum2(u64 v) {
    float lo, hi; unpk2(v, lo, hi); return lo + hi;
}

// ---------------- activations (accurate: ~1e-7) ----------------
__device__ __forceinline__ float sigf(float x) {
    return __fdividef(1.0f, 1.0f + __expf(-x));
}
__device__ __forceinline__ float tanhfast(float x) {
    return 1.0f - __fdividef(2.0f, 1.0f + __expf(2.0f * x));
}

// Gate update. Lane l<16 owns gates (i_l, g_l); lane l+16 owns (f_l, o_l) and the
// (c_l, h_l) state. Only the i*g product crosses halves (1 xor-shfl).
__device__ __forceinline__ void gate_update(float gA, float gB, bool lo, float& c, float& h) {
    const unsigned FULL = 0xffffffffu;
    float sA = sigf(gA);                       // sig(i) or sig(f)
    float y  = lo ? 2.0f * gB : gB;            // tanh(g)=2*sig(2g)-1 ; sig(o)
    float s  = sigf(y);
    float vB = lo ? 2.0f * s - 1.0f : s;       // tanh(g) | sig(o)
    float ps = lo ? sA * vB : vB;              // i*g (lo) ; dummy (hi)
    float pr = __shfl_xor_sync(FULL, ps, 16);  // hi lanes receive i*g
    c = sA * c + pr;                           // hi: sig(f)*c + i*g   (lo: bounded junk)
    h = vB * tanhfast(c);                      // hi: sig(o)*tanh(c)
}

// ---------------- kernel 1: xg = x @ W_ih0^T + (b_ih0 + b_hh0) ----------------
// 128 threads = 4 quarter-groups x 32 lanes; each thread: 4 rows x 16 gates, f32x2.
#define XPAD 132
__global__ __launch_bounds__(128) void k_inproj(const float* __restrict__ x,
                                                const float* __restrict__ Wih,
                                                const float* __restrict__ bih,
                                                const float* __restrict__ bhh) {
    __shared__ __align__(16) float Wt[DIN * G4];        // Wt[d*64 + g]
    __shared__ __align__(16) float xsT[DIN * XPAD];     // xsT[d*132 + r]
    __shared__ __align__(16) float bsh[G4];
    const int tid = threadIdx.x;

    for (int i = tid; i < DIN * G4; i += 128) {
        int d = i >> 6, g = i & 63;
        Wt[i] = Wih[g * DIN + d];
    }
    if (tid < G4) bsh[tid] = bih[tid] + bhh[tid];
    const int row0 = blockIdx.x * 128;
    for (int i = tid; i < 128 * DIN; i += 128) {
        int r = i / DIN, d = i - r * DIN;
        xsT[d * XPAD + r] = x[(size_t)row0 * DIN + i];
    }
    __syncthreads();

    const int q = tid >> 5, lane = tid & 31;

    u64 acc[4][8];
#pragma unroll
    for (int r = 0; r < 4; ++r)
#pragma unroll
        for (int p = 0; p < 8; ++p) acc[r][p] = 0ull;

    for (int d = 0; d < DIN; ++d) {
        float4 xv = *(const float4*)&xsT[d * XPAD + lane * 4];
        const float4* wq = (const float4*)&Wt[d * G4 + q * 16];
        u64 w[8];
#pragma unroll
        for (int j = 0; j < 4; ++j) {
            float4 wv = wq[j];
            w[2 * j]     = pk2(wv.x, wv.y);
            w[2 * j + 1] = pk2(wv.z, wv.w);
        }
        float xr[4] = {xv.x, xv.y, xv.z, xv.w};
#pragma unroll
        for (int r = 0; r < 4; ++r) {
            u64 xs2 = pk2(xr[r], xr[r]);
#pragma unroll
            for (int p = 0; p < 8; ++p) acc[r][p] = ffma2(w[p], xs2, acc[r][p]);
        }
    }

    const float4* bq = (const float4*)&bsh[q * 16];
#pragma unroll
    for (int r = 0; r < 4; ++r) {
        int row = row0 + lane * 4 + r;
        float4* o = (float4*)(g_xg + (size_t)row * G4 + q * 16);
#pragma unroll
        for (int j = 0; j < 4; ++j) {
            float l0, h0, l1, h1;
            unpk2(acc[r][2 * j], l0, h0);
            unpk2(acc[r][2 * j + 1], l1, h1);
            float4 bb = bq[j];
            o[j] = make_float4(l0 + bb.x, h0 + bb.y, l1 + bb.z, h1 + bb.w);
        }
    }
}

// ---------------- kernel 2: fused 3-layer LSTM, 1 warp per batch ----------------
// Pipeline: iter it computes h0(it), h1(it-1), h2(it-2). h broadcast via a single
// 48-float smem buffer (hi-lanes STS after update; matvec reads pre-packed u64
// pairs with broadcast LDS.64). All matvec reads precede all writes within a step,
// so a single buffer matches R3's register-state semantics exactly.

struct S3 { float c0, h0, c1, h1, c2, h2; };

template<bool L0, bool L1, bool L2>
__device__ __forceinline__ void step3(
    S3& s, float xA, float xB,
    const u64* wh0A, const u64* wh0B,
    const u64* wi1A, const u64* wi1B, const u64* wh1A, const u64* wh1B,
    const u64* wi2A, const u64* wi2B, const u64* wh2A, const u64* wh2B,
    u64 B1A, u64 B1B, u64 B2A, u64 B2B,
    int lane, bool lo, float* hsh, float* st_ptr)
{
    const u64* H0 = (const u64*)hsh;        // h0(it-1) pairs
    const u64* H1 = H0 + 8;                 // h1(it-2) pairs
    const u64* H2 = H0 + 16;                // h2(it-3) pairs
    u64 aA0 = pk2(xA, 0.f), aB0 = pk2(xB, 0.f);
    u64 aA1 = B1A, aB1 = B1B, aA2 = B2A, aB2 = B2B;
#pragma unroll
    for (int kp = 0; kp < 8; ++kp) {
        u64 h0v = H0[kp], h1v = H1[kp], h2v = H2[kp];   // broadcast LDS.64
        aA0 = ffma2(wh0A[kp], h0v, aA0);  aB0 = ffma2(wh0B[kp], h0v, aB0);
        aA1 = ffma2(wi1A[kp], h0v, aA1);  aB1 = ffma2(wi1B[kp], h0v, aB1);
        aA1 = ffma2(wh1A[kp], h1v, aA1);  aB1 = ffma2(wh1B[kp], h1v, aB1);
        aA2 = ffma2(wi2A[kp], h1v, aA2);  aB2 = ffma2(wi2B[kp], h1v, aB2);
        aA2 = ffma2(wh2A[kp], h2v, aA2);  aB2 = ffma2(wh2B[kp], h2v, aB2);
    }
    if (L0) {
        gate_update(hsum2(aA0), hsum2(aB0), lo, s.c0, s.h0);
        if (!lo) hsh[lane - 16] = s.h0;                 // h0(it)
    }
    if (L1) {
        gate_update(hsum2(aA1), hsum2(aB1), lo, s.c1, s.h1);
        if (!lo) hsh[16 + lane - 16] = s.h1;            // h1(it-1)
    }
    if (L2) {
        gate_update(hsum2(aA2), hsum2(aB2), lo, s.c2, s.h2);
        if (!lo) {
            hsh[32 + lane - 16] = s.h2;                 // h2(it-2)
            st_ptr[lane - 16] = s.h2;
        }
    }
    __syncwarp();   // fence: this step's STS visible to next step's LDS
}

__global__ __launch_bounds__(32, 1) void k_lstm3(
    const float* __restrict__ Whh0,
    const float* __restrict__ Wih1, const float* __restrict__ Whh1,
    const float* __restrict__ bih1, const float* __restrict__ bhh1,
    const float* __restrict__ Wih2, const float* __restrict__ Whh2,
    const float* __restrict__ bih2, const float* __restrict__ bhh2) {
    __shared__ __align__(16) float hsh[48];   // h0[16] | h1[16] | h2[16]
    const int lane = threadIdx.x;
    const int b = blockIdx.x;
    const int gA = lane, gB = lane + 32;
    const bool lo = lane < 16;

    for (int i = lane; i < 48; i += 32) hsh[i] = 0.0f;
    __syncwarp();

    u64 wh0A[8], wh0B[8], wh1A[8], wh1B[8], wh2A[8], wh2B[8];
    u64 wi1A[8], wi1B[8], wi2A[8], wi2B[8];
#pragma unroll
    for (int kp = 0; kp < 8; ++kp) {
        wh0A[kp] = pk2(Whh0[gA * 16 + 2 * kp], Whh0[gA * 16 + 2 * kp + 1]);
        wh0B[kp] = pk2(Whh0[gB * 16 + 2 * kp], Whh0[gB * 16 + 2 * kp + 1]);
        wh1A[kp] = pk2(Whh1[gA * 16 + 2 * kp], Whh1[gA * 16 + 2 * kp + 1]);
        wh1B[kp] = pk2(Whh1[gB * 16 + 2 * kp], Whh1[gB * 16 + 2 * kp + 1]);
        wh2A[kp] = pk2(Whh2[gA * 16 + 2 * kp], Whh2[gA * 16 + 2 * kp + 1]);
        wh2B[kp] = pk2(Whh2[gB * 16 + 2 * kp], Whh2[gB * 16 + 2 * kp + 1]);
        wi1A[kp] = pk2(Wih1[gA * 16 + 2 * kp], Wih1[gA * 16 + 2 * kp + 1]);
        wi1B[kp] = pk2(Wih1[gB * 16 + 2 * kp], Wih1[gB * 16 + 2 * kp + 1]);
        wi2A[kp] = pk2(Wih2[gA * 16 + 2 * kp], Wih2[gA * 16 + 2 * kp + 1]);
        wi2B[kp] = pk2(Wih2[gB * 16 + 2 * kp], Wih2[gB * 16 + 2 * kp + 1]);
    }
    const u64 B1A = pk2(bih1[gA] + bhh1[gA], 0.f);
    const u64 B1B = pk2(bih1[gB] + bhh1[gB], 0.f);
    const u64 B2A = pk2(bih2[gA] + bhh2[gA], 0.f);
    const u64 B2B = pk2(bih2[gB] + bhh2[gB], 0.f);

    S3 s = {0.f, 0.f, 0.f, 0.f, 0.f, 0.f};

    const float* px = g_xg + (size_t)b * SEQT * G4;
    float* ph2 = g_h2 + (size_t)b * SEQT * HID;

#define STEP(L0v, L1v, L2v, xa, xb, sp) \
    step3<L0v, L1v, L2v>(s, xa, xb, wh0A, wh0B, wi1A, wi1B, wh1A, wh1B, \
                         wi2A, wi2B, wh2A, wh2B, B1A, B1B, B2A, B2B, lane, lo, hsh, sp)

    // ---- prologue: it = 0..3 (guarded layers), init prefetch ring for 4..7
    float pfA[4], pfB[4];
    {
        float xA, xB;
        xA = px[0 * G4 + gA]; xB = px[0 * G4 + gB];
        STEP(true, false, false, xA, xB, ph2);
        xA = px[1 * G4 + gA]; xB = px[1 * G4 + gB];
        STEP(true, true, false, xA, xB, ph2);
        xA = px[2 * G4 + gA]; xB = px[2 * G4 + gB];
        STEP(true, true, true, xA, xB, ph2 + 0 * HID);
        xA = px[3 * G4 + gA]; xB = px[3 * G4 + gB];
        STEP(true, true, true, xA, xB, ph2 + 1 * HID);
#pragma unroll
        for (int u = 0; u < 4; ++u) {
            pfA[u] = px[(4 + u) * G4 + gA];
            pfB[u] = px[(4 + u) * G4 + gB];
        }
    }

    // ---- steady state: it = 4..2043, branch-free, prefetch it+4 (<= 2047)
    const float* pxa = px + gA + 8 * G4;
    const float* pxb = px + gB + 8 * G4;
    float* pst = ph2 + 2 * HID;            // store target for it=4 -> h2(2)
    for (int itb = 4; itb < 2044; itb += 4) {
#pragma unroll
        for (int u = 0; u < 4; ++u) {
            float xA = pfA[u], xB = pfB[u];
            pfA[u] = pxa[u * G4];
            pfB[u] = pxb[u * G4];
            STEP(true, true, true, xA, xB, pst);
            pst += HID;
        }
        pxa += 4 * G4;
        pxb += 4 * G4;
    }

    // ---- tail: it = 2044..2049 (ring holds xg[2044..2047])
    {
        STEP(true, true, true, pfA[0], pfB[0], ph2 + 2042 * HID);
        STEP(true, true, true, pfA[1], pfB[1], ph2 + 2043 * HID);
        STEP(true, true, true, pfA[2], pfB[2], ph2 + 2044 * HID);
        STEP(true, true, true, pfA[3], pfB[3], ph2 + 2045 * HID);
        STEP(false, true, true, 0.f, 0.f, ph2 + 2046 * HID);
        STEP(false, false, true, 0.f, 0.f, ph2 + 2047 * HID);
    }
#undef STEP
}

// ---------------- kernel 3: masked per-channel partial sums (deterministic) ----------------
__global__ __launch_bounds__(256) void k_stats(const int* __restrict__ len) {
    __shared__ float r1[256], r2[256];
    const int tid = threadIdx.x;
    const int t0 = blockIdx.x * 256 + tid;
    const int E = BT * HID;
    float s1 = 0.f, s2 = 0.f;
    for (int e = t0; e < E; e += NRED * 256) {
        int bt = e >> 4;
        int bb = bt >> 11;
        int ti = bt & 2047;
        float v = (ti < len[bb]) ? g_h2[e] : 0.f;
        s1 += v; s2 += v * v;
    }
    r1[tid] = s1; r2[tid] = s2;
    __syncthreads();
    for (int s = 128; s >= 16; s >>= 1) {
        if (tid < s) { r1[tid] += r1[tid + s]; r2[tid] += r2[tid + s]; }
        __syncthreads();
    }
    if (tid < 16) {
        g_part[blockIdx.x * 32 + tid]      = r1[tid];
        g_part[blockIdx.x * 32 + 16 + tid] = r2[tid];
    }
}

// ---------------- kernel 4: final BN stats -> scale/shift (parallel) ----------------
__global__ __launch_bounds__(512) void k_finalize(const float* __restrict__ gamma,
                                                  const float* __restrict__ beta) {
    __shared__ double r1[512], r2[512];
    const int tid = threadIdx.x;
    const int c = tid & 15;
    const int g0 = tid >> 4;
    double s1 = 0.0, s2 = 0.0;
    for (int g = g0; g < NRED; g += 32) {
        s1 += (double)g_part[g * 32 + c];
        s2 += (double)g_part[g * 32 + 16 + c];
    }
    r1[tid] = s1; r2[tid] = s2;
    __syncthreads();
    for (int s = 256; s >= 16; s >>= 1) {
        if (tid < s) { r1[tid] += r1[tid + s]; r2[tid] += r2[tid + s]; }
        __syncthreads();
    }
    if (tid < 16) {
        const double N = (double)BT;
        double mean = r1[tid] / N;
        double var = r2[tid] / N - mean * mean;
        float scale = gamma[tid] * (float)(1.0 / sqrt(var + 1e-5));
        float shift = beta[tid] - (float)mean * scale;
        g_stats[tid] = scale;
        g_stats[16 + tid] = shift;
    }
}

// ---------------- kernel 5: mask + normalize + FC ----------------
__global__ __launch_bounds__(256) void k_fc(const int* __restrict__ len,
                                            const float* __restrict__ fcw,
                                            const float* __restrict__ fcb,
                                            float* __restrict__ out) {
    __shared__ float sw[64], sb[4], ssc[16], ssh[16];
    const int tid = threadIdx.x;
    if (tid < 64) sw[tid] = fcw[tid];
    if (tid < 4) sb[tid] = fcb[tid];
    if (tid >= 64 && tid < 80)  ssc[tid - 64] = g_stats[tid - 64];
    if (tid >= 80 && tid < 96)  ssh[tid - 80] = g_stats[16 + (tid - 80)];
    __syncthreads();

    const int bt = blockIdx.x * 256 + tid;
    const int bb = bt >> 11, ti = bt & 2047;
    const bool valid = ti < len[bb];

    const float4* h4 = (const float4*)(g_h2 + (size_t)bt * HID);
    float y[16];
#pragma unroll
    for (int q = 0; q < 4; ++q) {
        float4 v = h4[q];
        y[q * 4 + 0] = v.x; y[q * 4 + 1] = v.y; y[q * 4 + 2] = v.z; y[q * 4 + 3] = v.w;
    }
    float o0 = sb[0], o1 = sb[1], o2 = sb[2], o3 = sb[3];
#pragma unroll
    for (int c = 0; c < 16; ++c) {
        float hv = valid ? y[c] : 0.f;
        float n = hv * ssc[c] + ssh[c];
        o0 += n * sw[0 * 16 + c];
        o1 += n * sw[1 * 16 + c];
        o2 += n * sw[2 * 16 + c];
        o3 += n * sw[3 * 16 + c];
    }
    ((float4*)out)[bt] = make_float4(o0, o1, o2, o3);
}

// ---------------- launch ----------------
extern "C" void kernel_launch(void* const* d_in, const int* in_sizes, int n_in,
                              void* d_out, int out_size) {
    const float* x      = (const float*)d_in[0];
    const int*   length = (const int*)d_in[1];
    const float* Wih0 = (const float*)d_in[2],  *Whh0 = (const float*)d_in[3];
    const float* bih0 = (const float*)d_in[4],  *bhh0 = (const float*)d_in[5];
    const float* Wih1 = (const float*)d_in[6],  *Whh1 = (const float*)d_in[7];
    const float* bih1 = (const float*)d_in[8],  *bhh1 = (const float*)d_in[9];
    const float* Wih2 = (const float*)d_in[10], *Whh2 = (const float*)d_in[11];
    const float* bih2 = (const float*)d_in[12], *bhh2 = (const float*)d_in[13];
    const float* gamma = (const float*)d_in[14], *beta = (const float*)d_in[15];
    const float* fcw   = (const float*)d_in[16], *fcb  = (const float*)d_in[17];

    k_inproj<<<BT / 128, 128>>>(x, Wih0, bih0, bhh0);
    k_lstm3<<<BATCH, 32>>>(Whh0, Wih1, Whh1, bih1, bhh1, Wih2, Whh2, bih2, bhh2);
    k_stats<<<NRED, 256>>>(length);
    k_finalize<<<1, 512>>>(gamma, beta);
    k_fc<<<BT / 256, 256>>>(length, fcw, fcb, (float*)d_out);
}

// round 15
// speedup vs baseline: 1.1447x; 1.1447x over previous
#include <cuda_runtime.h>
#include <math.h>

#define BATCH 256
#define SEQT  2048
#define DIN   57
#define HID   16
#define G4    64
#define BT    (BATCH*SEQT)
#define NRED  512

typedef unsigned long long u64;

// ---------------- scratch (device globals; no allocs allowed) ----------------
__device__ float g_xg[(size_t)BT * G4];     // 128 MiB: layer-0 pre-gates
__device__ float g_h2[(size_t)BT * HID];    //  32 MiB: layer-2 hidden outputs
__device__ float g_state[BATCH * 16 * 6];   // chunk-carried LSTM state (hi-lane units)
__device__ float g_part[NRED * 32];         // per-block partial sums (s1 | s2)
__device__ float g_stats[32];               // scale[16] | shift[16]

// ---------------- f32x2 packed helpers ----------------
__device__ __forceinline__ u64 pk2(float lo, float hi) {
    u64 r; asm("mov.b64 %0, {%1, %2};" : "=l"(r) : "f"(lo), "f"(hi)); return r;
}
__device__ __forceinline__ void unpk2(u64 v, float& lo, float& hi) {
    asm("mov.b64 {%0, %1}, %2;" : "=f"(lo), "=f"(hi) : "l"(v));
}
__device__ __forceinline__ u64 ffma2(u64 a, u64 b, u64 c) {
    u64 r; asm("fma.rn.f32x2 %0, %1, %2, %3;" : "=l"(r) : "l"(a), "l"(b), "l"(c)); return r;
}
__device__ __forceinline__ float hsum2(u64 v) {
    float lo, hi; unpk2(v, lo, hi); return lo + hi;
}

// ---------------- activations (accurate: ~1e-7) ----------------
__device__ __forceinline__ float sigf(float x) {
    return __fdividef(1.0f, 1.0f + __expf(-x));
}
__device__ __forceinline__ float tanhfast(float x) {
    return 1.0f - __fdividef(2.0f, 1.0f + __expf(2.0f * x));
}

// Gate update (1 cross-half shfl). Lane l<16 owns gates (i_l, g_l); lane 16+j owns
// (f_j, o_j) and the REAL (c_j, h_j) state. Lo-lane c,h are bounded junk.
__device__ __forceinline__ void gate_update(float gA, float gB, bool lo, float& c, float& h) {
    const unsigned FULL = 0xffffffffu;
    float sA = sigf(gA);                       // sig(i) | sig(f)
    float y  = lo ? 2.0f * gB : gB;
    float s  = sigf(y);
    float vB = lo ? 2.0f * s - 1.0f : s;       // tanh(g) | sig(o)
    float ps = lo ? sA * vB : vB;              // i*g (lo) ; dummy (hi)
    float pr = __shfl_xor_sync(FULL, ps, 16);  // hi lanes receive i*g
    c = sA * c + pr;                           // hi: sig(f)*c + i*g
    h = vB * tanhfast(c);                      // hi: sig(o)*tanh(c)
}

// ---------------- kernel 1: xg = x @ W_ih0^T + (b_ih0 + b_hh0) ----------------
#define XPAD 132
__global__ __launch_bounds__(128) void k_inproj(const float* __restrict__ x,
                                                const float* __restrict__ Wih,
                                                const float* __restrict__ bih,
                                                const float* __restrict__ bhh) {
    __shared__ __align__(16) float Wt[DIN * G4];
    __shared__ __align__(16) float xsT[DIN * XPAD];
    __shared__ __align__(16) float bsh[G4];
    const int tid = threadIdx.x;

    for (int i = tid; i < DIN * G4; i += 128) {
        int d = i >> 6, g = i & 63;
        Wt[i] = Wih[g * DIN + d];
    }
    if (tid < G4) bsh[tid] = bih[tid] + bhh[tid];
    const int row0 = blockIdx.x * 128;
    for (int i = tid; i < 128 * DIN; i += 128) {
        int r = i / DIN, d = i - r * DIN;
        xsT[d * XPAD + r] = x[(size_t)row0 * DIN + i];
    }
    __syncthreads();

    const int q = tid >> 5, lane = tid & 31;

    u64 acc[4][8];
#pragma unroll
    for (int r = 0; r < 4; ++r)
#pragma unroll
        for (int p = 0; p < 8; ++p) acc[r][p] = 0ull;

    for (int d = 0; d < DIN; ++d) {
        float4 xv = *(const float4*)&xsT[d * XPAD + lane * 4];
        const float4* wq = (const float4*)&Wt[d * G4 + q * 16];
        u64 w[8];
#pragma unroll
        for (int j = 0; j < 4; ++j) {
            float4 wv = wq[j];
            w[2 * j]     = pk2(wv.x, wv.y);
            w[2 * j + 1] = pk2(wv.z, wv.w);
        }
        float xr[4] = {xv.x, xv.y, xv.z, xv.w};
#pragma unroll
        for (int r = 0; r < 4; ++r) {
            u64 xs2 = pk2(xr[r], xr[r]);
#pragma unroll
            for (int p = 0; p < 8; ++p) acc[r][p] = ffma2(w[p], xs2, acc[r][p]);
        }
    }

    const float4* bq = (const float4*)&bsh[q * 16];
#pragma unroll
    for (int r = 0; r < 4; ++r) {
        int row = row0 + lane * 4 + r;
        float4* o = (float4*)(g_xg + (size_t)row * G4 + q * 16);
#pragma unroll
        for (int j = 0; j < 4; ++j) {
            float l0, h0, l1, h1;
            unpk2(acc[r][2 * j], l0, h0);
            unpk2(acc[r][2 * j + 1], l1, h1);
            float4 bb = bq[j];
            o[j] = make_float4(l0 + bb.x, h0 + bb.y, l1 + bb.z, h1 + bb.w);
        }
    }
}

// ---------------- kernel 2: fused 3-layer LSTM, 1 warp/batch, 8 chunk launches ----
// Pipelined step it: h0(it), h1(it-1), h2(it-2). h broadcast via shfl from hi lanes.

struct S3 { float c0, h0, c1, h1, c2, h2; };

template<bool L0, bool L1, bool L2>
__device__ __forceinline__ void step3(
    S3& s, float xA, float xB,
    const u64* wh0A, const u64* wh0B,
    const u64* wi1A, const u64* wi1B, const u64* wh1A, const u64* wh1B,
    const u64* wi2A, const u64* wi2B, const u64* wh2A, const u64* wh2B,
    u64 B1A, u64 B1B, u64 B2A, u64 B2B,
    int lane, bool lo, float* st_ptr)
{
    const unsigned FULL = 0xffffffffu;
    u64 aA0 = pk2(xA, 0.f), aB0 = pk2(xB, 0.f);
    u64 aA1 = B1A, aB1 = B1B, aA2 = B2A, aB2 = B2B;
#pragma unroll
    for (int kp = 0; kp < 8; ++kp) {
        float h0a = __shfl_sync(FULL, s.h0, 16 + 2 * kp);
        float h0b = __shfl_sync(FULL, s.h0, 16 + 2 * kp + 1);
        float h1a = __shfl_sync(FULL, s.h1, 16 + 2 * kp);
        float h1b = __shfl_sync(FULL, s.h1, 16 + 2 * kp + 1);
        float h2a = __shfl_sync(FULL, s.h2, 16 + 2 * kp);
        float h2b = __shfl_sync(FULL, s.h2, 16 + 2 * kp + 1);
        u64 h0p = pk2(h0a, h0b);
        u64 h1p = pk2(h1a, h1b);
        u64 h2p = pk2(h2a, h2b);
        aA0 = ffma2(wh0A[kp], h0p, aA0);  aB0 = ffma2(wh0B[kp], h0p, aB0);
        aA1 = ffma2(wi1A[kp], h0p, aA1);  aB1 = ffma2(wi1B[kp], h0p, aB1);
        aA1 = ffma2(wh1A[kp], h1p, aA1);  aB1 = ffma2(wh1B[kp], h1p, aB1);
        aA2 = ffma2(wi2A[kp], h1p, aA2);  aB2 = ffma2(wi2B[kp], h1p, aB2);
        aA2 = ffma2(wh2A[kp], h2p, aA2);  aB2 = ffma2(wh2B[kp], h2p, aB2);
    }
    if (L0) gate_update(hsum2(aA0), hsum2(aB0), lo, s.c0, s.h0);
    if (L1) gate_update(hsum2(aA1), hsum2(aB1), lo, s.c1, s.h1);
    if (L2) {
        gate_update(hsum2(aA2), hsum2(aB2), lo, s.c2, s.h2);
        if (!lo) st_ptr[lane - 16] = s.h2;
    }
}

__global__ __launch_bounds__(32, 1) void k_lstm3(
    const float* __restrict__ Whh0,
    const float* __restrict__ Wih1, const float* __restrict__ Whh1,
    const float* __restrict__ bih1, const float* __restrict__ bhh1,
    const float* __restrict__ Wih2, const float* __restrict__ Whh2,
    const float* __restrict__ bih2, const float* __restrict__ bhh2,
    int it0, int isFirst, int isLast) {
    const int lane = threadIdx.x;
    const int b = blockIdx.x;
    const int gA = lane, gB = lane + 32;
    const bool lo = lane < 16;

    u64 wh0A[8], wh0B[8], wh1A[8], wh1B[8], wh2A[8], wh2B[8];
    u64 wi1A[8], wi1B[8], wi2A[8], wi2B[8];
#pragma unroll
    for (int kp = 0; kp < 8; ++kp) {
        wh0A[kp] = pk2(Whh0[gA * 16 + 2 * kp], Whh0[gA * 16 + 2 * kp + 1]);
        wh0B[kp] = pk2(Whh0[gB * 16 + 2 * kp], Whh0[gB * 16 + 2 * kp + 1]);
        wh1A[kp] = pk2(Whh1[gA * 16 + 2 * kp], Whh1[gA * 16 + 2 * kp + 1]);
        wh1B[kp] = pk2(Whh1[gB * 16 + 2 * kp], Whh1[gB * 16 + 2 * kp + 1]);
        wh2A[kp] = pk2(Whh2[gA * 16 + 2 * kp], Whh2[gA * 16 + 2 * kp + 1]);
        wh2B[kp] = pk2(Whh2[gB * 16 + 2 * kp], Whh2[gB * 16 + 2 * kp + 1]);
        wi1A[kp] = pk2(Wih1[gA * 16 + 2 * kp], Wih1[gA * 16 + 2 * kp + 1]);
        wi1B[kp] = pk2(Wih1[gB * 16 + 2 * kp], Wih1[gB * 16 + 2 * kp + 1]);
        wi2A[kp] = pk2(Wih2[gA * 16 + 2 * kp], Wih2[gA * 16 + 2 * kp + 1]);
        wi2B[kp] = pk2(Wih2[gB * 16 + 2 * kp], Wih2[gB * 16 + 2 * kp + 1]);
    }
    const u64 B1A = pk2(bih1[gA] + bhh1[gA], 0.f);
    const u64 B1B = pk2(bih1[gB] + bhh1[gB], 0.f);
    const u64 B2A = pk2(bih2[gA] + bhh2[gA], 0.f);
    const u64 B2B = pk2(bih2[gB] + bhh2[gB], 0.f);

    S3 s = {0.f, 0.f, 0.f, 0.f, 0.f, 0.f};
    float* stp = g_state + ((size_t)b * 16 + (lane & 15)) * 6;
    if (!isFirst && !lo) {          // restore hi-lane state; lo lanes restart at 0 (junk)
        s.c0 = stp[0]; s.h0 = stp[1];
        s.c1 = stp[2]; s.h1 = stp[3];
        s.c2 = stp[4]; s.h2 = stp[5];
    }

    const float* px = g_xg + (size_t)b * SEQT * G4;
    float* ph2 = g_h2 + (size_t)b * SEQT * HID;

#define STEP(L0v, L1v, L2v, xa, xb, sp) \
    step3<L0v, L1v, L2v>(s, xa, xb, wh0A, wh0B, wi1A, wi1B, wh1A, wh1B, \
                         wi2A, wi2B, wh2A, wh2B, B1A, B1B, B2A, B2B, lane, lo, sp)

    int itS = it0;                          // ring start (first steady it)
    if (isFirst) {                          // guarded warm-up its 0..3
        float xA, xB;
        xA = px[0 * G4 + gA]; xB = px[0 * G4 + gB];
        STEP(true, false, false, xA, xB, ph2);
        xA = px[1 * G4 + gA]; xB = px[1 * G4 + gB];
        STEP(true, true, false, xA, xB, ph2);
        xA = px[2 * G4 + gA]; xB = px[2 * G4 + gB];
        STEP(true, true, true, xA, xB, ph2 + 0 * HID);
        xA = px[3 * G4 + gA]; xB = px[3 * G4 + gB];
        STEP(true, true, true, xA, xB, ph2 + 1 * HID);
        itS = 4;
    }

    // prefetch ring for its itS..itS+3  (itS+3 <= 1795, always in range)
    float pfA[4], pfB[4];
#pragma unroll
    for (int u = 0; u < 4; ++u) {
        pfA[u] = px[(itS + u) * G4 + gA];
        pfB[u] = px[(itS + u) * G4 + gB];
    }

    // steady: nSteady steps (multiple of 4); prefetch it+4 (max 2047, no clamp needed)
    const int nSteady = (isFirst || isLast) ? 252 : 256;
    const float* pxa = px + gA + (size_t)(itS + 4) * G4;
    const float* pxb = px + gB + (size_t)(itS + 4) * G4;
    float* pst = ph2 + (size_t)(itS - 2) * HID;
    for (int n = 0; n < nSteady; n += 4) {
#pragma unroll
        for (int u = 0; u < 4; ++u) {
            float xA = pfA[u], xB = pfB[u];
            pfA[u] = pxa[u * G4];
            pfB[u] = pxb[u * G4];
            STEP(true, true, true, xA, xB, pst);
            pst += HID;
        }
        pxa += 4 * G4;
        pxb += 4 * G4;
    }

    if (isLast) {   // its 2044..2047 consume the ring, then guarded 2048, 2049
        STEP(true, true, true, pfA[0], pfB[0], ph2 + 2042 * HID);
        STEP(true, true, true, pfA[1], pfB[1], ph2 + 2043 * HID);
        STEP(true, true, true, pfA[2], pfB[2], ph2 + 2044 * HID);
        STEP(true, true, true, pfA[3], pfB[3], ph2 + 2045 * HID);
        STEP(false, true, true, 0.f, 0.f, ph2 + 2046 * HID);
        STEP(false, false, true, 0.f, 0.f, ph2 + 2047 * HID);
    } else if (!lo) {                       // save hi-lane state for next chunk
        stp[0] = s.c0; stp[1] = s.h0;
        stp[2] = s.c1; stp[3] = s.h1;
        stp[4] = s.c2; stp[5] = s.h2;
    }
#undef STEP
}

// ---------------- kernel 3: masked per-channel partial sums (deterministic) ----------------
__global__ __launch_bounds__(256) void k_stats(const int* __restrict__ len) {
    __shared__ float r1[256], r2[256];
    const int tid = threadIdx.x;
    const int t0 = blockIdx.x * 256 + tid;
    const int E = BT * HID;
    float s1 = 0.f, s2 = 0.f;
    for (int e = t0; e < E; e += NRED * 256) {
        int bt = e >> 4;
        int bb = bt >> 11;
        int ti = bt & 2047;
        float v = (ti < len[bb]) ? g_h2[e] : 0.f;
        s1 += v; s2 += v * v;
    }
    r1[tid] = s1; r2[tid] = s2;
    __syncthreads();
    for (int s = 128; s >= 16; s >>= 1) {
        if (tid < s) { r1[tid] += r1[tid + s]; r2[tid] += r2[tid + s]; }
        __syncthreads();
    }
    if (tid < 16) {
        g_part[blockIdx.x * 32 + tid]      = r1[tid];
        g_part[blockIdx.x * 32 + 16 + tid] = r2[tid];
    }
}

// ---------------- kernel 4: final BN stats -> scale/shift (parallel) ----------------
__global__ __launch_bounds__(512) void k_finalize(const float* __restrict__ gamma,
                                                  const float* __restrict__ beta) {
    __shared__ double r1[512], r2[512];
    const int tid = threadIdx.x;
    const int c = tid & 15;
    const int g0 = tid >> 4;
    double s1 = 0.0, s2 = 0.0;
    for (int g = g0; g < NRED; g += 32) {
        s1 += (double)g_part[g * 32 + c];
        s2 += (double)g_part[g * 32 + 16 + c];
    }
    r1[tid] = s1; r2[tid] = s2;
    __syncthreads();
    for (int s = 256; s >= 16; s >>= 1) {
        if (tid < s) { r1[tid] += r1[tid + s]; r2[tid] += r2[tid + s]; }
        __syncthreads();
    }
    if (tid < 16) {
        const double N = (double)BT;
        double mean = r1[tid] / N;
        double var = r2[tid] / N - mean * mean;
        float scale = gamma[tid] * (float)(1.0 / sqrt(var + 1e-5));
        float shift = beta[tid] - (float)mean * scale;
        g_stats[tid] = scale;
        g_stats[16 + tid] = shift;
    }
}

// ---------------- kernel 5: mask + normalize + FC ----------------
__global__ __launch_bounds__(256) void k_fc(const int* __restrict__ len,
                                            const float* __restrict__ fcw,
                                            const float* __restrict__ fcb,
                                            float* __restrict__ out) {
    __shared__ float sw[64], sb[4], ssc[16], ssh[16];
    const int tid = threadIdx.x;
    if (tid < 64) sw[tid] = fcw[tid];
    if (tid < 4) sb[tid] = fcb[tid];
    if (tid >= 64 && tid < 80)  ssc[tid - 64] = g_stats[tid - 64];
    if (tid >= 80 && tid < 96)  ssh[tid - 80] = g_stats[16 + (tid - 80)];
    __syncthreads();

    const int bt = blockIdx.x * 256 + tid;
    const int bb = bt >> 11, ti = bt & 2047;
    const bool valid = ti < len[bb];

    const float4* h4 = (const float4*)(g_h2 + (size_t)bt * HID);
    float y[16];
#pragma unroll
    for (int q = 0; q < 4; ++q) {
        float4 v = h4[q];
        y[q * 4 + 0] = v.x; y[q * 4 + 1] = v.y; y[q * 4 + 2] = v.z; y[q * 4 + 3] = v.w;
    }
    float o0 = sb[0], o1 = sb[1], o2 = sb[2], o3 = sb[3];
#pragma unroll
    for (int c = 0; c < 16; ++c) {
        float hv = valid ? y[c] : 0.f;
        float n = hv * ssc[c] + ssh[c];
        o0 += n * sw[0 * 16 + c];
        o1 += n * sw[1 * 16 + c];
        o2 += n * sw[2 * 16 + c];
        o3 += n * sw[3 * 16 + c];
    }
    ((float4*)out)[bt] = make_float4(o0, o1, o2, o3);
}

// ---------------- launch ----------------
extern "C" void kernel_launch(void* const* d_in, const int* in_sizes, int n_in,
                              void* d_out, int out_size) {
    const float* x      = (const float*)d_in[0];
    const int*   length = (const int*)d_in[1];
    const float* Wih0 = (const float*)d_in[2],  *Whh0 = (const float*)d_in[3];
    const float* bih0 = (const float*)d_in[4],  *bhh0 = (const float*)d_in[5];
    const float* Wih1 = (const float*)d_in[6],  *Whh1 = (const float*)d_in[7];
    const float* bih1 = (const float*)d_in[8],  *bhh1 = (const float*)d_in[9];
    const float* Wih2 = (const float*)d_in[10], *Whh2 = (const float*)d_in[11];
    const float* bih2 = (const float*)d_in[12], *bhh2 = (const float*)d_in[13];
    const float* gamma = (const float*)d_in[14], *beta = (const float*)d_in[15];
    const float* fcw   = (const float*)d_in[16], *fcb  = (const float*)d_in[17];

    k_inproj<<<BT / 128, 128>>>(x, Wih0, bih0, bhh0);
    for (int q = 0; q < 8; ++q) {
        k_lstm3<<<BATCH, 32>>>(Whh0, Wih1, Whh1, bih1, bhh1,
                               Wih2, Whh2, bih2, bhh2,
                               q * 256, q == 0 ? 1 : 0, q == 7 ? 1 : 0);
    }
    k_stats<<<NRED, 256>>>(length);
    k_finalize<<<1, 512>>>(gamma, beta);
    k_fc<<<BT / 256, 256>>>(length, fcw, fcb, (float*)d_out);
}